// round 1
// baseline (speedup 1.0000x reference)
#include <cuda_runtime.h>
#include <math.h>

#define D_MODEL 512
#define NHEAD   8
#define HD      64
#define WIN     32
#define WFULL   (2 * WIN + 1)   // 65
#define BATCH   2
#define SEQ     2048

// Scratch (no cudaMalloc allowed)
__device__ float g_qkv[BATCH * SEQ * 3 * D_MODEL];   // [B*S, 1536]  (q | k | v)
__device__ float g_attn[BATCH * SEQ * D_MODEL];      // [B*S, 512]

// ---------------------------------------------------------------------------
// Tiled SGEMM with bias: C[M,N] = A[M,K] @ B[K,N] + bias[N]
// 64x64 tile, BK=16, 256 threads, 4x4 micro-tile.
// M % 64 == 0, N % 64 == 0, K % 16 == 0 assumed.
// ---------------------------------------------------------------------------
#define TS 64
#define KS 16

__global__ __launch_bounds__(256) void sgemm_bias(
    const float* __restrict__ A, const float* __restrict__ B,
    const float* __restrict__ bias, float* __restrict__ C,
    int M, int N, int K)
{
    __shared__ float As[KS][TS];
    __shared__ float Bs[KS][TS + 4];   // pad to dodge conflicts on 4-wide reads

    const int tid = threadIdx.x;
    const int tx = tid % 16;           // N direction
    const int ty = tid / 16;           // M direction
    const int bm = blockIdx.y * TS;
    const int bn = blockIdx.x * TS;

    float acc[4][4] = {};

    for (int k0 = 0; k0 < K; k0 += KS) {
        // Load A tile (64 rows x 16 cols), store transposed As[k][m]
        #pragma unroll
        for (int i = tid; i < TS * KS; i += 256) {
            int m = i / KS;
            int k = i % KS;
            As[k][m] = A[(size_t)(bm + m) * K + k0 + k];
        }
        // Load B tile (16 rows x 64 cols), Bs[k][n] — coalesced
        #pragma unroll
        for (int i = tid; i < TS * KS; i += 256) {
            int k = i / TS;
            int n = i % TS;
            Bs[k][n] = B[(size_t)(k0 + k) * N + bn + n];
        }
        __syncthreads();

        #pragma unroll
        for (int k = 0; k < KS; k++) {
            float a[4], b[4];
            #pragma unroll
            for (int i = 0; i < 4; i++) a[i] = As[k][ty * 4 + i];
            #pragma unroll
            for (int j = 0; j < 4; j++) b[j] = Bs[k][tx * 4 + j];
            #pragma unroll
            for (int i = 0; i < 4; i++)
                #pragma unroll
                for (int j = 0; j < 4; j++)
                    acc[i][j] += a[i] * b[j];
        }
        __syncthreads();
    }

    #pragma unroll
    for (int i = 0; i < 4; i++) {
        int m = bm + ty * 4 + i;
        #pragma unroll
        for (int j = 0; j < 4; j++) {
            int n = bn + tx * 4 + j;
            C[(size_t)m * N + n] = acc[i][j] + bias[n];
        }
    }
}

// ---------------------------------------------------------------------------
// Sliding-window attention. One block per (b, s). 256 threads = 8 warps.
// qkv row layout: [q(512) | k(512) | v(512)], head h occupies cols h*64..h*64+63.
// ---------------------------------------------------------------------------
__global__ __launch_bounds__(256) void window_attn(
    const float* __restrict__ qkv, float* __restrict__ out)
{
    const int bs = blockIdx.x;              // b*SEQ + s
    const int s  = bs % SEQ;
    const int tid = threadIdx.x;

    __shared__ float sh_q[D_MODEL];         // 512
    __shared__ float sh_sc[NHEAD * WFULL];  // 8 * 65 = 520

    const float* row = qkv + (size_t)bs * (3 * D_MODEL);

    // Stage q
    #pragma unroll
    for (int i = tid; i < D_MODEL; i += 256)
        sh_q[i] = row[i];
    __syncthreads();

    const float scale = 0.125f;             // 1/sqrt(64)

    // Scores: 8*65 = 520 dot products over 64 dims
    for (int p = tid; p < NHEAD * WFULL; p += 256) {
        const int h = p / WFULL;
        const int j = p % WFULL;
        const int idx = s - WIN + j;
        float sc = -1e9f;
        if (idx >= 0 && idx < SEQ) {
            const float* krow = qkv + ((size_t)(bs - s + idx) * (3 * D_MODEL)) + D_MODEL + h * HD;
            const float* qh = sh_q + h * HD;
            float dot = 0.f;
            #pragma unroll
            for (int d = 0; d < HD; d++)
                dot += qh[d] * krow[d];
            sc = dot * scale;
        }
        sh_sc[p] = sc;
    }
    __syncthreads();

    // Softmax: warp w handles head w (65 values = 32 + 32 + 1)
    {
        const int w = tid / 32;
        const int lane = tid % 32;
        float* sc = sh_sc + w * WFULL;
        float v0 = sc[lane];
        float v1 = sc[32 + lane];
        float v2 = (lane == 0) ? sc[64] : -1e30f;

        float m = fmaxf(fmaxf(v0, v1), v2);
        #pragma unroll
        for (int off = 16; off > 0; off >>= 1)
            m = fmaxf(m, __shfl_xor_sync(0xffffffffu, m, off));

        float e0 = __expf(v0 - m);
        float e1 = __expf(v1 - m);
        float e2 = (lane == 0) ? __expf(v2 - m) : 0.f;
        float sum = e0 + e1 + e2;
        #pragma unroll
        for (int off = 16; off > 0; off >>= 1)
            sum += __shfl_xor_sync(0xffffffffu, sum, off);

        float inv = 1.0f / sum;
        sc[lane] = e0 * inv;
        sc[32 + lane] = e1 * inv;
        if (lane == 0) sc[64] = e2 * inv;
    }
    __syncthreads();

    // Output: out[h,d] = sum_j attn[h,j] * v[idx, h, d]
    const int j0 = (s - WIN < 0) ? (WIN - s) : 0;
    const int j1 = (s + WIN >= SEQ) ? (SEQ - s + WIN) : WFULL;  // exclusive

    for (int p = tid; p < D_MODEL; p += 256) {
        const int h = p / HD;
        const int d = p % HD;
        const float* sc = sh_sc + h * WFULL;
        float acc = 0.f;
        for (int j = j0; j < j1; j++) {
            const int idx = s - WIN + j;
            const float* vrow = qkv + ((size_t)(bs - s + idx) * (3 * D_MODEL)) + 2 * D_MODEL + h * HD;
            acc += sc[j] * vrow[d];
        }
        out[(size_t)bs * D_MODEL + p] = acc;
    }
}

// ---------------------------------------------------------------------------
extern "C" void kernel_launch(void* const* d_in, const int* in_sizes, int n_in,
                              void* d_out, int out_size)
{
    const float* x     = (const float*)d_in[0];   // [2,2048,512]
    const float* w_qkv = (const float*)d_in[1];   // [512,1536]
    const float* b_qkv = (const float*)d_in[2];   // [1536]
    const float* w_out = (const float*)d_in[3];   // [512,512]
    const float* b_out = (const float*)d_in[4];   // [512]
    float* out = (float*)d_out;                   // [2,2048,512]

    float* qkv;  cudaGetSymbolAddress((void**)&qkv,  g_qkv);
    float* attn; cudaGetSymbolAddress((void**)&attn, g_attn);

    const int M = BATCH * SEQ;        // 4096
    const int N1 = 3 * D_MODEL;       // 1536
    const int K = D_MODEL;            // 512

    // 1) QKV projection
    {
        dim3 grid(N1 / TS, M / TS);
        sgemm_bias<<<grid, 256>>>(x, w_qkv, b_qkv, qkv, M, N1, K);
    }
    // 2) Windowed attention
    {
        window_attn<<<M, 256>>>(qkv, attn);
    }
    // 3) Output projection
    {
        dim3 grid(D_MODEL / TS, M / TS);
        sgemm_bias<<<grid, 256>>>(attn, w_out, b_out, out, M, D_MODEL, K);
    }
}

// round 2
// speedup vs baseline: 2.9951x; 2.9951x over previous
#include <cuda_runtime.h>
#include <math.h>

#define D_MODEL 512
#define NHEAD   8
#define HD      64
#define WIN     32
#define BATCH   2
#define SEQ     2048

// Scratch (no cudaMalloc allowed)
__device__ float g_q[BATCH * NHEAD * SEQ * HD];
__device__ float g_k[BATCH * NHEAD * SEQ * HD];
__device__ float g_v[BATCH * NHEAD * SEQ * HD];
__device__ float g_attn[BATCH * SEQ * D_MODEL];

// ---------------------------------------------------------------------------
// SGEMM v2: 128x128 tile, BK=16, 256 threads, 8x8 micro-tile (split 4+4).
// C = A[M,K] @ B[K,N] + bias.  If SCATTER, writes qkv head-major instead.
// ---------------------------------------------------------------------------
template<bool SCATTER>
__global__ __launch_bounds__(256) void sgemm128(
    const float* __restrict__ A, const float* __restrict__ Bw,
    const float* __restrict__ bias, float* __restrict__ C,
    float* __restrict__ qo, float* __restrict__ ko, float* __restrict__ vo,
    int M, int N, int K)
{
    __shared__ float As[16][128];
    __shared__ float Bs[16][128];

    const int tid = threadIdx.x;
    const int bm = blockIdx.y * 128;
    const int bn = blockIdx.x * 128;

    // A tile loads: 128 rows x 16 k -> 2 float4 per thread
    const int ar = tid >> 1;
    const int ak = (tid & 1) * 8;
    // B tile loads: 16 rows x 128 n -> 2 float4 per thread
    const int br = tid >> 4;
    const int bc = (tid & 15) * 8;

    const int tx = tid & 15;
    const int ty = tid >> 4;

    float acc[8][8] = {};

    for (int k0 = 0; k0 < K; k0 += 16) {
        float4 a0 = *(const float4*)&A[(size_t)(bm + ar) * K + k0 + ak];
        float4 a1 = *(const float4*)&A[(size_t)(bm + ar) * K + k0 + ak + 4];
        float4 b0 = *(const float4*)&Bw[(size_t)(k0 + br) * N + bn + bc];
        float4 b1 = *(const float4*)&Bw[(size_t)(k0 + br) * N + bn + bc + 4];

        As[ak + 0][ar] = a0.x; As[ak + 1][ar] = a0.y;
        As[ak + 2][ar] = a0.z; As[ak + 3][ar] = a0.w;
        As[ak + 4][ar] = a1.x; As[ak + 5][ar] = a1.y;
        As[ak + 6][ar] = a1.z; As[ak + 7][ar] = a1.w;
        *(float4*)&Bs[br][bc]     = b0;
        *(float4*)&Bs[br][bc + 4] = b1;
        __syncthreads();

        #pragma unroll
        for (int kk = 0; kk < 16; kk++) {
            float a[8], b[8];
            *(float4*)&a[0] = *(const float4*)&As[kk][ty * 4];
            *(float4*)&a[4] = *(const float4*)&As[kk][64 + ty * 4];
            *(float4*)&b[0] = *(const float4*)&Bs[kk][tx * 4];
            *(float4*)&b[4] = *(const float4*)&Bs[kk][64 + tx * 4];
            #pragma unroll
            for (int i = 0; i < 8; i++)
                #pragma unroll
                for (int j = 0; j < 8; j++)
                    acc[i][j] += a[i] * b[j];
        }
        __syncthreads();
    }

    #pragma unroll
    for (int i = 0; i < 8; i++) {
        int m = bm + (i < 4 ? ty * 4 + i : 64 + ty * 4 + (i - 4));
        #pragma unroll
        for (int j = 0; j < 8; j++) {
            int n = bn + (j < 4 ? tx * 4 + j : 64 + tx * 4 + (j - 4));
            float val = acc[i][j] + bias[n];
            if (SCATTER) {
                int t  = n >> 9;
                int hh = (n >> 6) & 7;
                int dd = n & 63;
                int bb = m >> 11;       // m = b*SEQ + s
                int ss = m & 2047;
                size_t dst = ((size_t)(bb * NHEAD + hh) * SEQ + ss) * HD + dd;
                float* p = (t == 0) ? qo : (t == 1) ? ko : vo;
                p[dst] = val;
            } else {
                C[(size_t)m * N + n] = val;
            }
        }
    }
}

// ---------------------------------------------------------------------------
// Tiled sliding-window attention.
// Block = (s_tile of 64 queries, head, batch). 256 threads.
// Full 64x128 score matrix (window cols c = q + j, j in [0,64]), band-masked.
// ---------------------------------------------------------------------------
#define TQ 64
#define TC 128          // TQ + 2*WIN
#define QT_S 68         // Qt[HD][TQ] stride (aligned, conflict-safe)
#define KT_S 132        // Kt[HD][TC] stride
#define VB_S 68         // V [TC][HD] stride
#define P_S  132        // P  [TQ][TC] stride

#define ATTN_SMEM_FLOATS (HD * QT_S + TC * VB_S + TQ * P_S)  // 4352+8704+8448

__global__ __launch_bounds__(256) void window_attn(
    const float* __restrict__ gq, const float* __restrict__ gk,
    const float* __restrict__ gv, float* __restrict__ out)
{
    const int s0  = blockIdx.x * TQ;
    const int h   = blockIdx.y;
    const int b   = blockIdx.z;
    const int tid = threadIdx.x;
    const size_t base = (size_t)(b * NHEAD + h) * SEQ;

    extern __shared__ float smem[];
    float* Qt = smem;                  // [HD][QT_S] transposed: Qt[d][q]
    float* KV = smem + HD * QT_S;      // Kt[d][c] (KT_S) then V[c][d] (VB_S)
    float* P  = KV + TC * VB_S;        // [TQ][P_S]

    const int d  = tid & 63;
    const int r0 = tid >> 6;           // 0..3

    // Stage Q transposed: Qt[d][q]
    #pragma unroll
    for (int r = r0; r < TQ; r += 4)
        Qt[d * QT_S + r] = gq[(base + s0 + r) * HD + d];
    // Stage K transposed: Kt[d][c], c covers abs rows [s0-32, s0+95]
    #pragma unroll
    for (int c = r0; c < TC; c += 4) {
        int idx = s0 - WIN + c;
        float v = 0.f;
        if (idx >= 0 && idx < SEQ) v = gk[(base + idx) * HD + d];
        KV[d * KT_S + c] = v;
    }
    __syncthreads();

    // ---- Scores: S[64][128] = Qt^T @ Kt, 4q x (4+4)c micro-tile ----
    const int tx = tid & 15;
    const int ty = tid >> 4;
    {
        float acc[4][8] = {};
        #pragma unroll 8
        for (int dd = 0; dd < HD; dd++) {
            float a[4], bb[8];
            *(float4*)&a[0]  = *(const float4*)&Qt[dd * QT_S + ty * 4];
            *(float4*)&bb[0] = *(const float4*)&KV[dd * KT_S + tx * 4];
            *(float4*)&bb[4] = *(const float4*)&KV[dd * KT_S + 64 + tx * 4];
            #pragma unroll
            for (int i = 0; i < 4; i++)
                #pragma unroll
                for (int j = 0; j < 8; j++)
                    acc[i][j] += a[i] * bb[j];
        }
        #pragma unroll
        for (int i = 0; i < 4; i++) {
            *(float4*)&P[(ty * 4 + i) * P_S + tx * 4]      = *(float4*)&acc[i][0];
            *(float4*)&P[(ty * 4 + i) * P_S + 64 + tx * 4] = *(float4*)&acc[i][4];
        }
    }
    __syncthreads();

    // Stage V (overwrites K region; safe after sync) — overlapped with softmax
    #pragma unroll
    for (int c = r0; c < TC; c += 4) {
        int idx = s0 - WIN + c;
        float v = 0.f;
        if (idx >= 0 && idx < SEQ) v = gv[(base + idx) * HD + d];
        KV[c * VB_S + d] = v;
    }

    // ---- Masked softmax: warp w handles rows q = w, w+8, ... ----
    {
        const int w = tid >> 5, lane = tid & 31;
        const float scale = 0.125f;     // 1/sqrt(64)
        for (int q = w; q < TQ; q += 8) {
            float vals[4];
            #pragma unroll
            for (int k = 0; k < 4; k++) {
                int c = lane + k * 32;
                int idx = s0 - WIN + c;
                bool valid = (c >= q) && (c <= q + 2 * WIN) && (idx >= 0) && (idx < SEQ);
                vals[k] = valid ? P[q * P_S + c] * scale : -1e30f;
            }
            float m = fmaxf(fmaxf(vals[0], vals[1]), fmaxf(vals[2], vals[3]));
            #pragma unroll
            for (int off = 16; off > 0; off >>= 1)
                m = fmaxf(m, __shfl_xor_sync(0xffffffffu, m, off));
            float e[4], sum = 0.f;
            #pragma unroll
            for (int k = 0; k < 4; k++) { e[k] = __expf(vals[k] - m); sum += e[k]; }
            #pragma unroll
            for (int off = 16; off > 0; off >>= 1)
                sum += __shfl_xor_sync(0xffffffffu, sum, off);
            float inv = 1.0f / sum;
            #pragma unroll
            for (int k = 0; k < 4; k++)
                P[q * P_S + lane + k * 32] = e[k] * inv;
        }
    }
    __syncthreads();

    // ---- AV: out[64][64] = P[64][128] @ V[128][64], 4q x 4d micro ----
    {
        const int q0 = ty * 4, d0 = tx * 4;
        float acc[4][4] = {};
        #pragma unroll 4
        for (int c = 0; c < TC; c++) {
            float p[4];
            float4 vv = *(const float4*)&KV[c * VB_S + d0];
            #pragma unroll
            for (int i = 0; i < 4; i++) p[i] = P[(q0 + i) * P_S + c];
            #pragma unroll
            for (int i = 0; i < 4; i++) {
                acc[i][0] += p[i] * vv.x;
                acc[i][1] += p[i] * vv.y;
                acc[i][2] += p[i] * vv.z;
                acc[i][3] += p[i] * vv.w;
            }
        }
        #pragma unroll
        for (int i = 0; i < 4; i++) {
            size_t o = ((size_t)b * SEQ + s0 + q0 + i) * D_MODEL + h * HD + d0;
            *(float4*)&out[o] = *(float4*)&acc[i][0];
        }
    }
}

// ---------------------------------------------------------------------------
extern "C" void kernel_launch(void* const* d_in, const int* in_sizes, int n_in,
                              void* d_out, int out_size)
{
    const float* x     = (const float*)d_in[0];
    const float* w_qkv = (const float*)d_in[1];
    const float* b_qkv = (const float*)d_in[2];
    const float* w_out = (const float*)d_in[3];
    const float* b_out = (const float*)d_in[4];
    float* out = (float*)d_out;

    float *q, *k, *v, *attn;
    cudaGetSymbolAddress((void**)&q,    g_q);
    cudaGetSymbolAddress((void**)&k,    g_k);
    cudaGetSymbolAddress((void**)&v,    g_v);
    cudaGetSymbolAddress((void**)&attn, g_attn);

    const int M = BATCH * SEQ;     // 4096
    const int K = D_MODEL;         // 512

    // 1) QKV projection with head-major scatter
    {
        dim3 grid((3 * D_MODEL) / 128, M / 128);
        sgemm128<true><<<grid, 256>>>(x, w_qkv, b_qkv, nullptr, q, k, v,
                                      M, 3 * D_MODEL, K);
    }
    // 2) Windowed attention
    {
        static int smem_set = 0;
        cudaFuncSetAttribute(window_attn,
                             cudaFuncAttributeMaxDynamicSharedMemorySize,
                             ATTN_SMEM_FLOATS * 4);
        (void)smem_set;
        dim3 grid(SEQ / TQ, NHEAD, BATCH);
        window_attn<<<grid, 256, ATTN_SMEM_FLOATS * 4>>>(q, k, v, attn);
    }
    // 3) Output projection
    {
        dim3 grid(D_MODEL / 128, M / 128);
        sgemm128<false><<<grid, 256>>>(attn, w_out, b_out, out,
                                       nullptr, nullptr, nullptr,
                                       M, D_MODEL, K);
    }
}

// round 4
// speedup vs baseline: 5.6344x; 1.8812x over previous
#include <cuda_runtime.h>
#include <cstdint>
#include <math.h>

#define D_MODEL 512
#define NHEAD   8
#define HD      64
#define WIN     32
#define BATCH   2
#define SEQ     2048

// Scratch (no cudaMalloc allowed)
__device__ float g_q[BATCH * NHEAD * SEQ * HD];
__device__ float g_k[BATCH * NHEAD * SEQ * HD];
__device__ float g_v[BATCH * NHEAD * SEQ * HD];
__device__ float g_attn[BATCH * SEQ * D_MODEL];

// ---------------------------------------------------------------------------
// TF32 tensor-core GEMM: C[M,N] = A[M,K] @ B[K,N] + bias
// BM=256, BN=128, BK=32. 256 threads = 8 warps (4 M x 2 N), warp tile 64x64.
// mma.sync.aligned.m16n8k8.row.col.f32.tf32.tf32.f32, fp32 accumulate.
// Smem pads: A stride 36 (frag banks 4*gid+tig distinct),
//            B stride 136 (frag banks 8*tig+gid distinct).
// ---------------------------------------------------------------------------
#define BM 256
#define BN 128
#define BK 32
#define AS_S 36
#define BS_S 136
#define GEMM_SMEM_BYTES ((BM * AS_S + BK * BS_S) * 4)   // 54272

__device__ __forceinline__ float f2tf32(float f) {
    unsigned int u;
    asm("cvt.rna.tf32.f32 %0, %1;" : "=r"(u) : "f"(f));
    return __uint_as_float(u);
}

__device__ __forceinline__ void mma_tf32(float4& d,
    unsigned int a0, unsigned int a1, unsigned int a2, unsigned int a3,
    unsigned int b0, unsigned int b1)
{
    asm volatile(
        "mma.sync.aligned.m16n8k8.row.col.f32.tf32.tf32.f32 "
        "{%0,%1,%2,%3}, {%4,%5,%6,%7}, {%8,%9}, {%0,%1,%2,%3};\n"
        : "+f"(d.x), "+f"(d.y), "+f"(d.z), "+f"(d.w)
        : "r"(a0), "r"(a1), "r"(a2), "r"(a3), "r"(b0), "r"(b1));
}

template<bool SCATTER>
__global__ __launch_bounds__(256, 1) void mma_gemm(
    const float* __restrict__ A, const float* __restrict__ Bw,
    const float* __restrict__ bias, float* __restrict__ C,
    float* __restrict__ qo, float* __restrict__ ko, float* __restrict__ vo,
    int M, int N, int K)
{
    extern __shared__ float sm[];
    float* As = sm;                    // [BM][AS_S]
    float* Bs = sm + BM * AS_S;        // [BK][BS_S]

    const int tid  = threadIdx.x;
    const int bm   = blockIdx.y * BM;
    const int bn   = blockIdx.x * BN;
    const int w    = tid >> 5;
    const int wm   = w >> 1;           // 0..3
    const int wn   = w & 1;            // 0..1
    const int lane = tid & 31;
    const int gid  = lane >> 2;        // 0..7
    const int tig  = lane & 3;         // 0..3

    float4 acc[4][8];
    #pragma unroll
    for (int i = 0; i < 4; i++)
        #pragma unroll
        for (int j = 0; j < 8; j++)
            acc[i][j] = make_float4(0.f, 0.f, 0.f, 0.f);

    const int arow = tid >> 3;         // 0..31
    const int acol = (tid & 7) * 4;    // 0..28
    const int brow = tid >> 5;         // 0..7
    const int bcol = lane * 4;         // 0..124

    for (int k0 = 0; k0 < K; k0 += BK) {
        // Stage A: 256 rows x 32 k (8 passes of 32 rows)
        #pragma unroll
        for (int p = 0; p < 8; p++) {
            const int r = p * 32 + arow;
            float4 t = *(const float4*)&A[(size_t)(bm + r) * K + k0 + acol];
            t.x = f2tf32(t.x); t.y = f2tf32(t.y);
            t.z = f2tf32(t.z); t.w = f2tf32(t.w);
            *(float4*)&As[r * AS_S + acol] = t;
        }
        // Stage B: 32 k x 128 n (4 passes of 8 rows)
        #pragma unroll
        for (int p = 0; p < 4; p++) {
            const int r = p * 8 + brow;
            float4 t = *(const float4*)&Bw[(size_t)(k0 + r) * N + bn + bcol];
            t.x = f2tf32(t.x); t.y = f2tf32(t.y);
            t.z = f2tf32(t.z); t.w = f2tf32(t.w);
            *(float4*)&Bs[r * BS_S + bcol] = t;
        }
        __syncthreads();

        #pragma unroll
        for (int ks = 0; ks < 4; ks++) {
            const int kk = ks * 8;
            unsigned int af[4][4], bf[8][2];
            #pragma unroll
            for (int mf = 0; mf < 4; mf++) {
                const int mb = wm * 64 + mf * 16;
                af[mf][0] = __float_as_uint(As[(mb + gid)     * AS_S + kk + tig]);
                af[mf][1] = __float_as_uint(As[(mb + gid + 8) * AS_S + kk + tig]);
                af[mf][2] = __float_as_uint(As[(mb + gid)     * AS_S + kk + tig + 4]);
                af[mf][3] = __float_as_uint(As[(mb + gid + 8) * AS_S + kk + tig + 4]);
            }
            #pragma unroll
            for (int nf = 0; nf < 8; nf++) {
                const int nb = wn * 64 + nf * 8;
                bf[nf][0] = __float_as_uint(Bs[(kk + tig)     * BS_S + nb + gid]);
                bf[nf][1] = __float_as_uint(Bs[(kk + tig + 4) * BS_S + nb + gid]);
            }
            #pragma unroll
            for (int mf = 0; mf < 4; mf++)
                #pragma unroll
                for (int nf = 0; nf < 8; nf++)
                    mma_tf32(acc[mf][nf],
                             af[mf][0], af[mf][1], af[mf][2], af[mf][3],
                             bf[nf][0], bf[nf][1]);
        }
        __syncthreads();
    }

    // Epilogue: c0/c1 -> row gid, c2/c3 -> row gid+8; cols tig*2, tig*2+1
    #pragma unroll
    for (int mf = 0; mf < 4; mf++) {
        #pragma unroll
        for (int nf = 0; nf < 8; nf++) {
            const int m0 = bm + wm * 64 + mf * 16 + gid;
            const int n0 = bn + wn * 64 + nf * 8 + tig * 2;
            const float bs0 = bias[n0], bs1 = bias[n0 + 1];
            float2 top = make_float2(acc[mf][nf].x + bs0, acc[mf][nf].y + bs1);
            float2 bot = make_float2(acc[mf][nf].z + bs0, acc[mf][nf].w + bs1);
            if (SCATTER) {
                const int t  = n0 >> 9;
                const int hh = (n0 >> 6) & 7;
                const int dd = n0 & 63;
                float* p = (t == 0) ? qo : (t == 1) ? ko : vo;
                {
                    const int bb = m0 >> 11, ss = m0 & 2047;
                    *(float2*)&p[((size_t)(bb * NHEAD + hh) * SEQ + ss) * HD + dd] = top;
                }
                {
                    const int m1 = m0 + 8;
                    const int bb = m1 >> 11, ss = m1 & 2047;
                    *(float2*)&p[((size_t)(bb * NHEAD + hh) * SEQ + ss) * HD + dd] = bot;
                }
            } else {
                *(float2*)&C[(size_t)m0 * N + n0]       = top;
                *(float2*)&C[(size_t)(m0 + 8) * N + n0] = bot;
            }
        }
    }
}

// ---------------------------------------------------------------------------
// Tiled sliding-window attention (unchanged from R2).
// ---------------------------------------------------------------------------
#define TQ 64
#define TC 128
#define QT_S 68
#define KT_S 132
#define VB_S 68
#define P_S  132
#define ATTN_SMEM_FLOATS (HD * QT_S + TC * VB_S + TQ * P_S)

__global__ __launch_bounds__(256) void window_attn(
    const float* __restrict__ gq, const float* __restrict__ gk,
    const float* __restrict__ gv, float* __restrict__ out)
{
    const int s0  = blockIdx.x * TQ;
    const int h   = blockIdx.y;
    const int b   = blockIdx.z;
    const int tid = threadIdx.x;
    const size_t base = (size_t)(b * NHEAD + h) * SEQ;

    extern __shared__ float smem[];
    float* Qt = smem;
    float* KV = smem + HD * QT_S;
    float* P  = KV + TC * VB_S;

    const int d  = tid & 63;
    const int r0 = tid >> 6;

    #pragma unroll
    for (int r = r0; r < TQ; r += 4)
        Qt[d * QT_S + r] = gq[(base + s0 + r) * HD + d];
    #pragma unroll
    for (int c = r0; c < TC; c += 4) {
        int idx = s0 - WIN + c;
        float v = 0.f;
        if (idx >= 0 && idx < SEQ) v = gk[(base + idx) * HD + d];
        KV[d * KT_S + c] = v;
    }
    __syncthreads();

    const int tx = tid & 15;
    const int ty = tid >> 4;
    {
        float acc[4][8] = {};
        #pragma unroll 8
        for (int dd = 0; dd < HD; dd++) {
            float a[4], bb[8];
            *(float4*)&a[0]  = *(const float4*)&Qt[dd * QT_S + ty * 4];
            *(float4*)&bb[0] = *(const float4*)&KV[dd * KT_S + tx * 4];
            *(float4*)&bb[4] = *(const float4*)&KV[dd * KT_S + 64 + tx * 4];
            #pragma unroll
            for (int i = 0; i < 4; i++)
                #pragma unroll
                for (int j = 0; j < 8; j++)
                    acc[i][j] += a[i] * bb[j];
        }
        #pragma unroll
        for (int i = 0; i < 4; i++) {
            *(float4*)&P[(ty * 4 + i) * P_S + tx * 4]      = *(float4*)&acc[i][0];
            *(float4*)&P[(ty * 4 + i) * P_S + 64 + tx * 4] = *(float4*)&acc[i][4];
        }
    }
    __syncthreads();

    #pragma unroll
    for (int c = r0; c < TC; c += 4) {
        int idx = s0 - WIN + c;
        float v = 0.f;
        if (idx >= 0 && idx < SEQ) v = gv[(base + idx) * HD + d];
        KV[c * VB_S + d] = v;
    }

    {
        const int w = tid >> 5, lane = tid & 31;
        const float scale = 0.125f;
        for (int q = w; q < TQ; q += 8) {
            float vals[4];
            #pragma unroll
            for (int k = 0; k < 4; k++) {
                int c = lane + k * 32;
                int idx = s0 - WIN + c;
                bool valid = (c >= q) && (c <= q + 2 * WIN) && (idx >= 0) && (idx < SEQ);
                vals[k] = valid ? P[q * P_S + c] * scale : -1e30f;
            }
            float m = fmaxf(fmaxf(vals[0], vals[1]), fmaxf(vals[2], vals[3]));
            #pragma unroll
            for (int off = 16; off > 0; off >>= 1)
                m = fmaxf(m, __shfl_xor_sync(0xffffffffu, m, off));
            float e[4], sum = 0.f;
            #pragma unroll
            for (int k = 0; k < 4; k++) { e[k] = __expf(vals[k] - m); sum += e[k]; }
            #pragma unroll
            for (int off = 16; off > 0; off >>= 1)
                sum += __shfl_xor_sync(0xffffffffu, sum, off);
            float inv = 1.0f / sum;
            #pragma unroll
            for (int k = 0; k < 4; k++)
                P[q * P_S + lane + k * 32] = e[k] * inv;
        }
    }
    __syncthreads();

    {
        const int q0 = ty * 4, d0 = tx * 4;
        float acc[4][4] = {};
        #pragma unroll 4
        for (int c = 0; c < TC; c++) {
            float p[4];
            float4 vv = *(const float4*)&KV[c * VB_S + d0];
            #pragma unroll
            for (int i = 0; i < 4; i++) p[i] = P[(q0 + i) * P_S + c];
            #pragma unroll
            for (int i = 0; i < 4; i++) {
                acc[i][0] += p[i] * vv.x;
                acc[i][1] += p[i] * vv.y;
                acc[i][2] += p[i] * vv.z;
                acc[i][3] += p[i] * vv.w;
            }
        }
        #pragma unroll
        for (int i = 0; i < 4; i++) {
            size_t o = ((size_t)b * SEQ + s0 + q0 + i) * D_MODEL + h * HD + d0;
            *(float4*)&out[o] = *(float4*)&acc[i][0];
        }
    }
}

// ---------------------------------------------------------------------------
extern "C" void kernel_launch(void* const* d_in, const int* in_sizes, int n_in,
                              void* d_out, int out_size)
{
    const float* x     = (const float*)d_in[0];
    const float* w_qkv = (const float*)d_in[1];
    const float* b_qkv = (const float*)d_in[2];
    const float* w_out = (const float*)d_in[3];
    const float* b_out = (const float*)d_in[4];
    float* out = (float*)d_out;

    float *q, *k, *v, *attn;
    cudaGetSymbolAddress((void**)&q,    g_q);
    cudaGetSymbolAddress((void**)&k,    g_k);
    cudaGetSymbolAddress((void**)&v,    g_v);
    cudaGetSymbolAddress((void**)&attn, g_attn);

    const int M = BATCH * SEQ;     // 4096
    const int K = D_MODEL;         // 512

    cudaFuncSetAttribute(mma_gemm<true>,
                         cudaFuncAttributeMaxDynamicSharedMemorySize,
                         GEMM_SMEM_BYTES);
    cudaFuncSetAttribute(mma_gemm<false>,
                         cudaFuncAttributeMaxDynamicSharedMemorySize,
                         GEMM_SMEM_BYTES);
    cudaFuncSetAttribute(window_attn,
                         cudaFuncAttributeMaxDynamicSharedMemorySize,
                         ATTN_SMEM_FLOATS * 4);

    // 1) QKV projection (tf32 MMA) with head-major scatter
    {
        dim3 grid((3 * D_MODEL) / BN, M / BM);   // 12 x 16
        mma_gemm<true><<<grid, 256, GEMM_SMEM_BYTES>>>(
            x, w_qkv, b_qkv, nullptr, q, k, v, M, 3 * D_MODEL, K);
    }
    // 2) Windowed attention
    {
        dim3 grid(SEQ / TQ, NHEAD, BATCH);
        window_attn<<<grid, 256, ATTN_SMEM_FLOATS * 4>>>(q, k, v, attn);
    }
    // 3) Output projection (tf32 MMA)
    {
        dim3 grid(D_MODEL / BN, M / BM);         // 4 x 16
        mma_gemm<false><<<grid, 256, GEMM_SMEM_BYTES>>>(
            attn, w_out, b_out, out, nullptr, nullptr, nullptr,
            M, D_MODEL, K);
    }
}

// round 5
// speedup vs baseline: 6.8233x; 1.2110x over previous
#include <cuda_runtime.h>
#include <cstdint>
#include <math.h>

#define D_MODEL 512
#define NHEAD   8
#define HD      64
#define WIN     32
#define BATCH   2
#define SEQ     2048

// Scratch (no cudaMalloc allowed)
__device__ float g_q[BATCH * NHEAD * SEQ * HD];
__device__ float g_k[BATCH * NHEAD * SEQ * HD];
__device__ float g_v[BATCH * NHEAD * SEQ * HD];
__device__ float g_attn[BATCH * SEQ * D_MODEL];

// ---------------------------------------------------------------------------
// TF32 tensor-core GEMM, double-buffered: C[M,N] = A[M,K] @ B[K,N] + bias
// BM=128, BK=32, 256 threads = 8 warps. BN_=128: warps 2x4, warp tile 64x32.
// BN_=64: warps 4x2, warp tile 32x32. m16n8k8 tf32, fp32 accumulate.
// A smem stride 36 (frag banks 4*gid+tig distinct), B stride BN_+8 (≡8 mod 32,
// frag banks 8*tig+gid distinct).
// ---------------------------------------------------------------------------
#define BM 128
#define BK 32
#define AS_S 36

__device__ __forceinline__ float f2tf32(float f) {
    unsigned int u;
    asm("cvt.rna.tf32.f32 %0, %1;" : "=r"(u) : "f"(f));
    return __uint_as_float(u);
}

__device__ __forceinline__ void mma_tf32(float4& d,
    unsigned int a0, unsigned int a1, unsigned int a2, unsigned int a3,
    unsigned int b0, unsigned int b1)
{
    asm volatile(
        "mma.sync.aligned.m16n8k8.row.col.f32.tf32.tf32.f32 "
        "{%0,%1,%2,%3}, {%4,%5,%6,%7}, {%8,%9}, {%0,%1,%2,%3};\n"
        : "+f"(d.x), "+f"(d.y), "+f"(d.z), "+f"(d.w)
        : "r"(a0), "r"(a1), "r"(a2), "r"(a3), "r"(b0), "r"(b1));
}

template<int BN_, bool SCATTER>
__global__ __launch_bounds__(256, 2) void mma_gemm(
    const float* __restrict__ A, const float* __restrict__ Bw,
    const float* __restrict__ bias, float* __restrict__ C,
    float* __restrict__ qo, float* __restrict__ ko, float* __restrict__ vo,
    int M, int N, int K)
{
    constexpr int WM_WARPS = (BN_ == 128) ? 2 : 4;
    constexpr int WN_WARPS = 8 / WM_WARPS;
    constexpr int WT_M = BM / WM_WARPS;          // 64 or 32
    constexpr int WT_N = BN_ / WN_WARPS;         // 32
    constexpr int MF = WT_M / 16;                // 4 or 2
    constexpr int NF = WT_N / 8;                 // 4
    constexpr int BS_Sl = BN_ + 8;               // 136 or 72 (≡ 8 mod 32)
    constexpr int BUF = BM * AS_S + BK * BS_Sl;
    constexpr int BF4 = (BK * BN_) / 1024;       // B float4s per thread: 4 or 2
    constexpr int BROW_F4 = BN_ / 4;

    extern __shared__ float smbuf[];

    const int tid  = threadIdx.x;
    const int bm   = blockIdx.y * BM;
    const int bn   = blockIdx.x * BN_;
    const int w    = tid >> 5;
    const int wm   = w % WM_WARPS;
    const int wn   = w / WM_WARPS;
    const int lane = tid & 31;
    const int gid  = lane >> 2;
    const int tig  = lane & 3;

    float4 acc[MF][NF];
    #pragma unroll
    for (int i = 0; i < MF; i++)
        #pragma unroll
        for (int j = 0; j < NF; j++)
            acc[i][j] = make_float4(0.f, 0.f, 0.f, 0.f);

    float4 a_st[4], b_st[BF4];

    auto ldg_tiles = [&](int k0) {
        #pragma unroll
        for (int p = 0; p < 4; p++) {
            const int idx = p * 256 + tid;
            const int r = idx >> 3, c = (idx & 7) << 2;
            a_st[p] = *(const float4*)&A[(size_t)(bm + r) * K + k0 + c];
        }
        #pragma unroll
        for (int p = 0; p < BF4; p++) {
            const int idx = p * 256 + tid;
            const int r = idx / BROW_F4, c = (idx % BROW_F4) << 2;
            b_st[p] = *(const float4*)&Bw[(size_t)(k0 + r) * N + bn + c];
        }
    };
    auto sts_tiles = [&](float* base) {
        float* As = base;
        float* Bs = base + BM * AS_S;
        #pragma unroll
        for (int p = 0; p < 4; p++) {
            const int idx = p * 256 + tid;
            const int r = idx >> 3, c = (idx & 7) << 2;
            float4 t = a_st[p];
            t.x = f2tf32(t.x); t.y = f2tf32(t.y);
            t.z = f2tf32(t.z); t.w = f2tf32(t.w);
            *(float4*)&As[r * AS_S + c] = t;
        }
        #pragma unroll
        for (int p = 0; p < BF4; p++) {
            const int idx = p * 256 + tid;
            const int r = idx / BROW_F4, c = (idx % BROW_F4) << 2;
            float4 t = b_st[p];
            t.x = f2tf32(t.x); t.y = f2tf32(t.y);
            t.z = f2tf32(t.z); t.w = f2tf32(t.w);
            *(float4*)&Bs[r * BS_Sl + c] = t;
        }
    };
    auto compute = [&](const float* base) {
        const float* As = base;
        const float* Bs = base + BM * AS_S;
        #pragma unroll
        for (int ks = 0; ks < 4; ks++) {
            const int kk = ks * 8;
            unsigned int af[MF][4], bf[NF][2];
            #pragma unroll
            for (int mf = 0; mf < MF; mf++) {
                const int mb = wm * WT_M + mf * 16;
                af[mf][0] = __float_as_uint(As[(mb + gid)     * AS_S + kk + tig]);
                af[mf][1] = __float_as_uint(As[(mb + gid + 8) * AS_S + kk + tig]);
                af[mf][2] = __float_as_uint(As[(mb + gid)     * AS_S + kk + tig + 4]);
                af[mf][3] = __float_as_uint(As[(mb + gid + 8) * AS_S + kk + tig + 4]);
            }
            #pragma unroll
            for (int nf = 0; nf < NF; nf++) {
                const int nb = wn * WT_N + nf * 8;
                bf[nf][0] = __float_as_uint(Bs[(kk + tig)     * BS_Sl + nb + gid]);
                bf[nf][1] = __float_as_uint(Bs[(kk + tig + 4) * BS_Sl + nb + gid]);
            }
            #pragma unroll
            for (int mf = 0; mf < MF; mf++)
                #pragma unroll
                for (int nf = 0; nf < NF; nf++)
                    mma_tf32(acc[mf][nf],
                             af[mf][0], af[mf][1], af[mf][2], af[mf][3],
                             bf[nf][0], bf[nf][1]);
        }
    };

    // Pipeline: prefetch next tile's globals during current tile's MMAs.
    const int NIT = K / BK;
    ldg_tiles(0);
    sts_tiles(smbuf);
    __syncthreads();
    int cur = 0;
    for (int it = 0; it < NIT; it++) {
        if (it + 1 < NIT) ldg_tiles((it + 1) * BK);
        compute(smbuf + cur * BUF);
        if (it + 1 < NIT) {
            sts_tiles(smbuf + (cur ^ 1) * BUF);
            __syncthreads();
            cur ^= 1;
        }
    }

    // Epilogue
    #pragma unroll
    for (int mf = 0; mf < MF; mf++) {
        #pragma unroll
        for (int nf = 0; nf < NF; nf++) {
            const int m0 = bm + wm * WT_M + mf * 16 + gid;
            const int n0 = bn + wn * WT_N + nf * 8 + tig * 2;
            const float bs0 = bias[n0], bs1 = bias[n0 + 1];
            float2 top = make_float2(acc[mf][nf].x + bs0, acc[mf][nf].y + bs1);
            float2 bot = make_float2(acc[mf][nf].z + bs0, acc[mf][nf].w + bs1);
            if (SCATTER) {
                const int t  = n0 >> 9;
                const int hh = (n0 >> 6) & 7;
                const int dd = n0 & 63;
                float* p = (t == 0) ? qo : (t == 1) ? ko : vo;
                {
                    const int bb = m0 >> 11, ss = m0 & 2047;
                    *(float2*)&p[((size_t)(bb * NHEAD + hh) * SEQ + ss) * HD + dd] = top;
                }
                {
                    const int m1 = m0 + 8;
                    const int bb = m1 >> 11, ss = m1 & 2047;
                    *(float2*)&p[((size_t)(bb * NHEAD + hh) * SEQ + ss) * HD + dd] = bot;
                }
            } else {
                *(float2*)&C[(size_t)m0 * N + n0]       = top;
                *(float2*)&C[(size_t)(m0 + 8) * N + n0] = bot;
            }
        }
    }
}

#define QKV_SMEM ((BM * AS_S + BK * (128 + 8)) * 2 * 4)   // 71680
#define OUT_SMEM ((BM * AS_S + BK * (64 + 8)) * 2 * 4)    // 55296

// ---------------------------------------------------------------------------
// Tiled sliding-window attention (unchanged).
// ---------------------------------------------------------------------------
#define TQ 64
#define TC 128
#define QT_S 68
#define KT_S 132
#define VB_S 68
#define P_S  132
#define ATTN_SMEM_FLOATS (HD * QT_S + TC * VB_S + TQ * P_S)

__global__ __launch_bounds__(256) void window_attn(
    const float* __restrict__ gq, const float* __restrict__ gk,
    const float* __restrict__ gv, float* __restrict__ out)
{
    const int s0  = blockIdx.x * TQ;
    const int h   = blockIdx.y;
    const int b   = blockIdx.z;
    const int tid = threadIdx.x;
    const size_t base = (size_t)(b * NHEAD + h) * SEQ;

    extern __shared__ float smem[];
    float* Qt = smem;
    float* KV = smem + HD * QT_S;
    float* P  = KV + TC * VB_S;

    const int d  = tid & 63;
    const int r0 = tid >> 6;

    #pragma unroll
    for (int r = r0; r < TQ; r += 4)
        Qt[d * QT_S + r] = gq[(base + s0 + r) * HD + d];
    #pragma unroll
    for (int c = r0; c < TC; c += 4) {
        int idx = s0 - WIN + c;
        float v = 0.f;
        if (idx >= 0 && idx < SEQ) v = gk[(base + idx) * HD + d];
        KV[d * KT_S + c] = v;
    }
    __syncthreads();

    const int tx = tid & 15;
    const int ty = tid >> 4;
    {
        float acc[4][8] = {};
        #pragma unroll 8
        for (int dd = 0; dd < HD; dd++) {
            float a[4], bb[8];
            *(float4*)&a[0]  = *(const float4*)&Qt[dd * QT_S + ty * 4];
            *(float4*)&bb[0] = *(const float4*)&KV[dd * KT_S + tx * 4];
            *(float4*)&bb[4] = *(const float4*)&KV[dd * KT_S + 64 + tx * 4];
            #pragma unroll
            for (int i = 0; i < 4; i++)
                #pragma unroll
                for (int j = 0; j < 8; j++)
                    acc[i][j] += a[i] * bb[j];
        }
        #pragma unroll
        for (int i = 0; i < 4; i++) {
            *(float4*)&P[(ty * 4 + i) * P_S + tx * 4]      = *(float4*)&acc[i][0];
            *(float4*)&P[(ty * 4 + i) * P_S + 64 + tx * 4] = *(float4*)&acc[i][4];
        }
    }
    __syncthreads();

    #pragma unroll
    for (int c = r0; c < TC; c += 4) {
        int idx = s0 - WIN + c;
        float v = 0.f;
        if (idx >= 0 && idx < SEQ) v = gv[(base + idx) * HD + d];
        KV[c * VB_S + d] = v;
    }

    {
        const int w = tid >> 5, lane = tid & 31;
        const float scale = 0.125f;
        for (int q = w; q < TQ; q += 8) {
            float vals[4];
            #pragma unroll
            for (int k = 0; k < 4; k++) {
                int c = lane + k * 32;
                int idx = s0 - WIN + c;
                bool valid = (c >= q) && (c <= q + 2 * WIN) && (idx >= 0) && (idx < SEQ);
                vals[k] = valid ? P[q * P_S + c] * scale : -1e30f;
            }
            float m = fmaxf(fmaxf(vals[0], vals[1]), fmaxf(vals[2], vals[3]));
            #pragma unroll
            for (int off = 16; off > 0; off >>= 1)
                m = fmaxf(m, __shfl_xor_sync(0xffffffffu, m, off));
            float e[4], sum = 0.f;
            #pragma unroll
            for (int k = 0; k < 4; k++) { e[k] = __expf(vals[k] - m); sum += e[k]; }
            #pragma unroll
            for (int off = 16; off > 0; off >>= 1)
                sum += __shfl_xor_sync(0xffffffffu, sum, off);
            float inv = 1.0f / sum;
            #pragma unroll
            for (int k = 0; k < 4; k++)
                P[q * P_S + lane + k * 32] = e[k] * inv;
        }
    }
    __syncthreads();

    {
        const int q0 = ty * 4, d0 = tx * 4;
        float acc[4][4] = {};
        #pragma unroll 4
        for (int c = 0; c < TC; c++) {
            float p[4];
            float4 vv = *(const float4*)&KV[c * VB_S + d0];
            #pragma unroll
            for (int i = 0; i < 4; i++) p[i] = P[(q0 + i) * P_S + c];
            #pragma unroll
            for (int i = 0; i < 4; i++) {
                acc[i][0] += p[i] * vv.x;
                acc[i][1] += p[i] * vv.y;
                acc[i][2] += p[i] * vv.z;
                acc[i][3] += p[i] * vv.w;
            }
        }
        #pragma unroll
        for (int i = 0; i < 4; i++) {
            size_t o = ((size_t)b * SEQ + s0 + q0 + i) * D_MODEL + h * HD + d0;
            *(float4*)&out[o] = *(float4*)&acc[i][0];
        }
    }
}

// ---------------------------------------------------------------------------
extern "C" void kernel_launch(void* const* d_in, const int* in_sizes, int n_in,
                              void* d_out, int out_size)
{
    const float* x     = (const float*)d_in[0];
    const float* w_qkv = (const float*)d_in[1];
    const float* b_qkv = (const float*)d_in[2];
    const float* w_out = (const float*)d_in[3];
    const float* b_out = (const float*)d_in[4];
    float* out = (float*)d_out;

    float *q, *k, *v, *attn;
    cudaGetSymbolAddress((void**)&q,    g_q);
    cudaGetSymbolAddress((void**)&k,    g_k);
    cudaGetSymbolAddress((void**)&v,    g_v);
    cudaGetSymbolAddress((void**)&attn, g_attn);

    const int M = BATCH * SEQ;     // 4096
    const int K = D_MODEL;         // 512

    cudaFuncSetAttribute((const void*)mma_gemm<128, true>,
                         cudaFuncAttributeMaxDynamicSharedMemorySize, QKV_SMEM);
    cudaFuncSetAttribute((const void*)mma_gemm<64, false>,
                         cudaFuncAttributeMaxDynamicSharedMemorySize, OUT_SMEM);
    cudaFuncSetAttribute(window_attn,
                         cudaFuncAttributeMaxDynamicSharedMemorySize,
                         ATTN_SMEM_FLOATS * 4);

    // 1) QKV projection (tf32 MMA, double-buffered) with head-major scatter
    {
        dim3 grid((3 * D_MODEL) / 128, M / BM);   // 12 x 32 = 384 CTAs
        mma_gemm<128, true><<<grid, 256, QKV_SMEM>>>(
            x, w_qkv, b_qkv, nullptr, q, k, v, M, 3 * D_MODEL, K);
    }
    // 2) Windowed attention
    {
        dim3 grid(SEQ / TQ, NHEAD, BATCH);
        window_attn<<<grid, 256, ATTN_SMEM_FLOATS * 4>>>(q, k, v, attn);
    }
    // 3) Output projection (tf32 MMA, BN=64 for wave balance)
    {
        dim3 grid(D_MODEL / 64, M / BM);          // 8 x 32 = 256 CTAs
        mma_gemm<64, false><<<grid, 256, OUT_SMEM>>>(
            attn, w_out, b_out, out, nullptr, nullptr, nullptr,
            M, D_MODEL, K);
    }
}

// round 6
// speedup vs baseline: 7.5388x; 1.1049x over previous
#include <cuda_runtime.h>
#include <cstdint>
#include <math.h>

#define D_MODEL 512
#define NHEAD   8
#define HD      64
#define WIN     32
#define BATCH   2
#define SEQ     2048

// Scratch (no cudaMalloc allowed)
__device__ float g_q[BATCH * NHEAD * SEQ * HD];
__device__ float g_k[BATCH * NHEAD * SEQ * HD];
__device__ float g_v[BATCH * NHEAD * SEQ * HD];
__device__ float g_attn[BATCH * SEQ * D_MODEL];

__device__ __forceinline__ float f2tf32(float f) {
    unsigned int u;
    asm("cvt.rna.tf32.f32 %0, %1;" : "=r"(u) : "f"(f));
    return __uint_as_float(u);
}

__device__ __forceinline__ void mma_tf32(float4& d,
    unsigned int a0, unsigned int a1, unsigned int a2, unsigned int a3,
    unsigned int b0, unsigned int b1)
{
    asm volatile(
        "mma.sync.aligned.m16n8k8.row.col.f32.tf32.tf32.f32 "
        "{%0,%1,%2,%3}, {%4,%5,%6,%7}, {%8,%9}, {%0,%1,%2,%3};\n"
        : "+f"(d.x), "+f"(d.y), "+f"(d.z), "+f"(d.w)
        : "r"(a0), "r"(a1), "r"(a2), "r"(a3), "r"(b0), "r"(b1));
}

// ---------------------------------------------------------------------------
// TF32 tensor-core GEMM, double-buffered (unchanged from R5).
// ---------------------------------------------------------------------------
#define BM 128
#define BK 32
#define AS_S 36

template<int BN_, bool SCATTER>
__global__ __launch_bounds__(256, 2) void mma_gemm(
    const float* __restrict__ A, const float* __restrict__ Bw,
    const float* __restrict__ bias, float* __restrict__ C,
    float* __restrict__ qo, float* __restrict__ ko, float* __restrict__ vo,
    int M, int N, int K)
{
    constexpr int WM_WARPS = (BN_ == 128) ? 2 : 4;
    constexpr int WN_WARPS = 8 / WM_WARPS;
    constexpr int WT_M = BM / WM_WARPS;
    constexpr int WT_N = BN_ / WN_WARPS;
    constexpr int MF = WT_M / 16;
    constexpr int NF = WT_N / 8;
    constexpr int BS_Sl = BN_ + 8;
    constexpr int BUF = BM * AS_S + BK * BS_Sl;
    constexpr int BF4 = (BK * BN_) / 1024;
    constexpr int BROW_F4 = BN_ / 4;

    extern __shared__ float smbuf[];

    const int tid  = threadIdx.x;
    const int bm   = blockIdx.y * BM;
    const int bn   = blockIdx.x * BN_;
    const int w    = tid >> 5;
    const int wm   = w % WM_WARPS;
    const int wn   = w / WM_WARPS;
    const int lane = tid & 31;
    const int gid  = lane >> 2;
    const int tig  = lane & 3;

    float4 acc[MF][NF];
    #pragma unroll
    for (int i = 0; i < MF; i++)
        #pragma unroll
        for (int j = 0; j < NF; j++)
            acc[i][j] = make_float4(0.f, 0.f, 0.f, 0.f);

    float4 a_st[4], b_st[BF4];

    auto ldg_tiles = [&](int k0) {
        #pragma unroll
        for (int p = 0; p < 4; p++) {
            const int idx = p * 256 + tid;
            const int r = idx >> 3, c = (idx & 7) << 2;
            a_st[p] = *(const float4*)&A[(size_t)(bm + r) * K + k0 + c];
        }
        #pragma unroll
        for (int p = 0; p < BF4; p++) {
            const int idx = p * 256 + tid;
            const int r = idx / BROW_F4, c = (idx % BROW_F4) << 2;
            b_st[p] = *(const float4*)&Bw[(size_t)(k0 + r) * N + bn + c];
        }
    };
    auto sts_tiles = [&](float* base) {
        float* As = base;
        float* Bs = base + BM * AS_S;
        #pragma unroll
        for (int p = 0; p < 4; p++) {
            const int idx = p * 256 + tid;
            const int r = idx >> 3, c = (idx & 7) << 2;
            float4 t = a_st[p];
            t.x = f2tf32(t.x); t.y = f2tf32(t.y);
            t.z = f2tf32(t.z); t.w = f2tf32(t.w);
            *(float4*)&As[r * AS_S + c] = t;
        }
        #pragma unroll
        for (int p = 0; p < BF4; p++) {
            const int idx = p * 256 + tid;
            const int r = idx / BROW_F4, c = (idx % BROW_F4) << 2;
            float4 t = b_st[p];
            t.x = f2tf32(t.x); t.y = f2tf32(t.y);
            t.z = f2tf32(t.z); t.w = f2tf32(t.w);
            *(float4*)&Bs[r * BS_Sl + c] = t;
        }
    };
    auto compute = [&](const float* base) {
        const float* As = base;
        const float* Bs = base + BM * AS_S;
        #pragma unroll
        for (int ks = 0; ks < 4; ks++) {
            const int kk = ks * 8;
            unsigned int af[MF][4], bf[NF][2];
            #pragma unroll
            for (int mf = 0; mf < MF; mf++) {
                const int mb = wm * WT_M + mf * 16;
                af[mf][0] = __float_as_uint(As[(mb + gid)     * AS_S + kk + tig]);
                af[mf][1] = __float_as_uint(As[(mb + gid + 8) * AS_S + kk + tig]);
                af[mf][2] = __float_as_uint(As[(mb + gid)     * AS_S + kk + tig + 4]);
                af[mf][3] = __float_as_uint(As[(mb + gid + 8) * AS_S + kk + tig + 4]);
            }
            #pragma unroll
            for (int nf = 0; nf < NF; nf++) {
                const int nb = wn * WT_N + nf * 8;
                bf[nf][0] = __float_as_uint(Bs[(kk + tig)     * BS_Sl + nb + gid]);
                bf[nf][1] = __float_as_uint(Bs[(kk + tig + 4) * BS_Sl + nb + gid]);
            }
            #pragma unroll
            for (int mf = 0; mf < MF; mf++)
                #pragma unroll
                for (int nf = 0; nf < NF; nf++)
                    mma_tf32(acc[mf][nf],
                             af[mf][0], af[mf][1], af[mf][2], af[mf][3],
                             bf[nf][0], bf[nf][1]);
        }
    };

    const int NIT = K / BK;
    ldg_tiles(0);
    sts_tiles(smbuf);
    __syncthreads();
    int cur = 0;
    for (int it = 0; it < NIT; it++) {
        if (it + 1 < NIT) ldg_tiles((it + 1) * BK);
        compute(smbuf + cur * BUF);
        if (it + 1 < NIT) {
            sts_tiles(smbuf + (cur ^ 1) * BUF);
            __syncthreads();
            cur ^= 1;
        }
    }

    #pragma unroll
    for (int mf = 0; mf < MF; mf++) {
        #pragma unroll
        for (int nf = 0; nf < NF; nf++) {
            const int m0 = bm + wm * WT_M + mf * 16 + gid;
            const int n0 = bn + wn * WT_N + nf * 8 + tig * 2;
            const float bs0 = bias[n0], bs1 = bias[n0 + 1];
            float2 top = make_float2(acc[mf][nf].x + bs0, acc[mf][nf].y + bs1);
            float2 bot = make_float2(acc[mf][nf].z + bs0, acc[mf][nf].w + bs1);
            if (SCATTER) {
                const int t  = n0 >> 9;
                const int hh = (n0 >> 6) & 7;
                const int dd = n0 & 63;
                float* p = (t == 0) ? qo : (t == 1) ? ko : vo;
                {
                    const int bb = m0 >> 11, ss = m0 & 2047;
                    *(float2*)&p[((size_t)(bb * NHEAD + hh) * SEQ + ss) * HD + dd] = top;
                }
                {
                    const int m1 = m0 + 8;
                    const int bb = m1 >> 11, ss = m1 & 2047;
                    *(float2*)&p[((size_t)(bb * NHEAD + hh) * SEQ + ss) * HD + dd] = bot;
                }
            } else {
                *(float2*)&C[(size_t)m0 * N + n0]       = top;
                *(float2*)&C[(size_t)(m0 + 8) * N + n0] = bot;
            }
        }
    }
}

#define QKV_SMEM ((BM * AS_S + BK * (128 + 8)) * 2 * 4)   // 71680
#define OUT_SMEM ((BM * AS_S + BK * (64 + 8)) * 2 * 4)    // 55296

// ---------------------------------------------------------------------------
// Sliding-window attention, tf32 MMA version.
// Block = (64-query tile, head, batch), 256 threads = 8 warps.
// GEMM1: S[64,128] = Q[64,64] @ K^T (K stored [c][d]).
// Softmax (band mask), P holds tf32-rounded probabilities.
// GEMM2: O[64,64] = P[64,128] @ V[128,64] (V stored [c][d]).
// Strides: Q 68, K 68, V 72, P 132 -> all fragment accesses conflict-free.
// ---------------------------------------------------------------------------
#define TQ 64
#define TC 128
#define QS_S 68
#define KS_S 68
#define VS_S 72
#define P_S  132
#define KV_UNION (TC * VS_S)                 // max(128*68, 128*72) = 9216
#define ATTN_SMEM_FLOATS (TQ * QS_S + KV_UNION + TQ * P_S)   // 22016
#define ATTN_SMEM_BYTES  (ATTN_SMEM_FLOATS * 4)              // 88064

__global__ __launch_bounds__(256, 2) void window_attn_mma(
    const float* __restrict__ gq, const float* __restrict__ gk,
    const float* __restrict__ gv, float* __restrict__ out)
{
    const int s0  = blockIdx.x * TQ;
    const int h   = blockIdx.y;
    const int b   = blockIdx.z;
    const int tid = threadIdx.x;
    const size_t base = (size_t)(b * NHEAD + h) * SEQ;

    extern __shared__ float smem[];
    float* Qs = smem;                   // [TQ][QS_S]
    float* KV = smem + TQ * QS_S;       // K [TC][KS_S] then V [TC][VS_S]
    float* P  = KV + KV_UNION;          // [TQ][P_S]

    const int d  = tid & 63;
    const int r0 = tid >> 6;            // 0..3
    const int w    = tid >> 5;
    const int lane = tid & 31;
    const int gid  = lane >> 2;
    const int tig  = lane & 3;
    const int wm   = w & 1;             // 2 M-warps
    const int wn   = w >> 1;            // 4 N-warps

    // Stage Q (scale folded in) and K, both cvt to tf32.
    #pragma unroll
    for (int r = r0; r < TQ; r += 4)
        Qs[r * QS_S + d] = f2tf32(gq[(base + s0 + r) * HD + d] * 0.125f);
    #pragma unroll
    for (int c = r0; c < TC; c += 4) {
        const int idx = s0 - WIN + c;
        float val = 0.f;
        if (idx >= 0 && idx < SEQ) val = gk[(base + idx) * HD + d];
        KV[c * KS_S + d] = f2tf32(val);
    }
    __syncthreads();

    // ---- GEMM1: S = Q @ K^T. Warp tile 32x32 (MF=2, NF=4), K=64. ----
    {
        float4 acc[2][4];
        #pragma unroll
        for (int i = 0; i < 2; i++)
            #pragma unroll
            for (int j = 0; j < 4; j++)
                acc[i][j] = make_float4(0.f, 0.f, 0.f, 0.f);

        #pragma unroll
        for (int ks = 0; ks < 8; ks++) {
            const int kk = ks * 8;
            unsigned int af[2][4], bf[4][2];
            #pragma unroll
            for (int mf = 0; mf < 2; mf++) {
                const int mb = wm * 32 + mf * 16;
                af[mf][0] = __float_as_uint(Qs[(mb + gid)     * QS_S + kk + tig]);
                af[mf][1] = __float_as_uint(Qs[(mb + gid + 8) * QS_S + kk + tig]);
                af[mf][2] = __float_as_uint(Qs[(mb + gid)     * QS_S + kk + tig + 4]);
                af[mf][3] = __float_as_uint(Qs[(mb + gid + 8) * QS_S + kk + tig + 4]);
            }
            #pragma unroll
            for (int nf = 0; nf < 4; nf++) {
                const int nb = wn * 32 + nf * 8;
                bf[nf][0] = __float_as_uint(KV[(nb + gid) * KS_S + kk + tig]);
                bf[nf][1] = __float_as_uint(KV[(nb + gid) * KS_S + kk + tig + 4]);
            }
            #pragma unroll
            for (int mf = 0; mf < 2; mf++)
                #pragma unroll
                for (int nf = 0; nf < 4; nf++)
                    mma_tf32(acc[mf][nf],
                             af[mf][0], af[mf][1], af[mf][2], af[mf][3],
                             bf[nf][0], bf[nf][1]);
        }
        #pragma unroll
        for (int mf = 0; mf < 2; mf++) {
            #pragma unroll
            for (int nf = 0; nf < 4; nf++) {
                const int m0 = wm * 32 + mf * 16 + gid;
                const int n0 = wn * 32 + nf * 8 + tig * 2;
                *(float2*)&P[m0 * P_S + n0]       = make_float2(acc[mf][nf].x, acc[mf][nf].y);
                *(float2*)&P[(m0 + 8) * P_S + n0] = make_float2(acc[mf][nf].z, acc[mf][nf].w);
            }
        }
    }
    __syncthreads();

    // Stage V (overwrites K region) — overlaps softmax below.
    #pragma unroll
    for (int c = r0; c < TC; c += 4) {
        const int idx = s0 - WIN + c;
        float val = 0.f;
        if (idx >= 0 && idx < SEQ) val = gv[(base + idx) * HD + d];
        KV[c * VS_S + d] = f2tf32(val);
    }

    // ---- Masked softmax (scale already folded into Q). Warp per row. ----
    {
        for (int q = w; q < TQ; q += 8) {
            float vals[4];
            #pragma unroll
            for (int k = 0; k < 4; k++) {
                const int c = lane + k * 32;
                const int idx = s0 - WIN + c;
                const bool valid = (c >= q) && (c <= q + 2 * WIN) && (idx >= 0) && (idx < SEQ);
                vals[k] = valid ? P[q * P_S + c] : -1e30f;
            }
            float m = fmaxf(fmaxf(vals[0], vals[1]), fmaxf(vals[2], vals[3]));
            #pragma unroll
            for (int off = 16; off > 0; off >>= 1)
                m = fmaxf(m, __shfl_xor_sync(0xffffffffu, m, off));
            float e[4], sum = 0.f;
            #pragma unroll
            for (int k = 0; k < 4; k++) { e[k] = __expf(vals[k] - m); sum += e[k]; }
            #pragma unroll
            for (int off = 16; off > 0; off >>= 1)
                sum += __shfl_xor_sync(0xffffffffu, sum, off);
            const float inv = 1.0f / sum;
            #pragma unroll
            for (int k = 0; k < 4; k++)
                P[q * P_S + lane + k * 32] = f2tf32(e[k] * inv);
        }
    }
    __syncthreads();

    // ---- GEMM2: O = P @ V. Warp tile 32x16 (MF=2, NF=2), K=128. ----
    {
        float4 acc[2][2];
        #pragma unroll
        for (int i = 0; i < 2; i++)
            #pragma unroll
            for (int j = 0; j < 2; j++)
                acc[i][j] = make_float4(0.f, 0.f, 0.f, 0.f);

        #pragma unroll 4
        for (int ks = 0; ks < 16; ks++) {
            const int kk = ks * 8;
            unsigned int af[2][4], bf[2][2];
            #pragma unroll
            for (int mf = 0; mf < 2; mf++) {
                const int mb = wm * 32 + mf * 16;
                af[mf][0] = __float_as_uint(P[(mb + gid)     * P_S + kk + tig]);
                af[mf][1] = __float_as_uint(P[(mb + gid + 8) * P_S + kk + tig]);
                af[mf][2] = __float_as_uint(P[(mb + gid)     * P_S + kk + tig + 4]);
                af[mf][3] = __float_as_uint(P[(mb + gid + 8) * P_S + kk + tig + 4]);
            }
            #pragma unroll
            for (int nf = 0; nf < 2; nf++) {
                const int nb = wn * 16 + nf * 8;
                bf[nf][0] = __float_as_uint(KV[(kk + tig)     * VS_S + nb + gid]);
                bf[nf][1] = __float_as_uint(KV[(kk + tig + 4) * VS_S + nb + gid]);
            }
            #pragma unroll
            for (int mf = 0; mf < 2; mf++)
                #pragma unroll
                for (int nf = 0; nf < 2; nf++)
                    mma_tf32(acc[mf][nf],
                             af[mf][0], af[mf][1], af[mf][2], af[mf][3],
                             bf[nf][0], bf[nf][1]);
        }
        #pragma unroll
        for (int mf = 0; mf < 2; mf++) {
            #pragma unroll
            for (int nf = 0; nf < 2; nf++) {
                const int m0 = wm * 32 + mf * 16 + gid;
                const int n0 = wn * 16 + nf * 8 + tig * 2;
                size_t o0 = ((size_t)b * SEQ + s0 + m0) * D_MODEL + h * HD + n0;
                *(float2*)&out[o0] = make_float2(acc[mf][nf].x, acc[mf][nf].y);
                size_t o1 = ((size_t)b * SEQ + s0 + m0 + 8) * D_MODEL + h * HD + n0;
                *(float2*)&out[o1] = make_float2(acc[mf][nf].z, acc[mf][nf].w);
            }
        }
    }
}

// ---------------------------------------------------------------------------
extern "C" void kernel_launch(void* const* d_in, const int* in_sizes, int n_in,
                              void* d_out, int out_size)
{
    const float* x     = (const float*)d_in[0];
    const float* w_qkv = (const float*)d_in[1];
    const float* b_qkv = (const float*)d_in[2];
    const float* w_out = (const float*)d_in[3];
    const float* b_out = (const float*)d_in[4];
    float* out = (float*)d_out;

    float *q, *k, *v, *attn;
    cudaGetSymbolAddress((void**)&q,    g_q);
    cudaGetSymbolAddress((void**)&k,    g_k);
    cudaGetSymbolAddress((void**)&v,    g_v);
    cudaGetSymbolAddress((void**)&attn, g_attn);

    const int M = BATCH * SEQ;     // 4096
    const int K = D_MODEL;         // 512

    cudaFuncSetAttribute((const void*)mma_gemm<128, true>,
                         cudaFuncAttributeMaxDynamicSharedMemorySize, QKV_SMEM);
    cudaFuncSetAttribute((const void*)mma_gemm<64, false>,
                         cudaFuncAttributeMaxDynamicSharedMemorySize, OUT_SMEM);
    cudaFuncSetAttribute(window_attn_mma,
                         cudaFuncAttributeMaxDynamicSharedMemorySize, ATTN_SMEM_BYTES);

    // 1) QKV projection (tf32 MMA, double-buffered) with head-major scatter
    {
        dim3 grid((3 * D_MODEL) / 128, M / BM);   // 12 x 32 = 384 CTAs
        mma_gemm<128, true><<<grid, 256, QKV_SMEM>>>(
            x, w_qkv, b_qkv, nullptr, q, k, v, M, 3 * D_MODEL, K);
    }
    // 2) Windowed attention (tf32 MMA)
    {
        dim3 grid(SEQ / TQ, NHEAD, BATCH);        // 32 x 8 x 2 = 512 CTAs
        window_attn_mma<<<grid, 256, ATTN_SMEM_BYTES>>>(q, k, v, attn);
    }
    // 3) Output projection (tf32 MMA, BN=64 for wave balance)
    {
        dim3 grid(D_MODEL / 64, M / BM);          // 8 x 32 = 256 CTAs
        mma_gemm<64, false><<<grid, 256, OUT_SMEM>>>(
            attn, w_out, b_out, out, nullptr, nullptr, nullptr,
            M, D_MODEL, K);
    }
}

// round 8
// speedup vs baseline: 7.5598x; 1.0028x over previous
#include <cuda_runtime.h>
#include <cstdint>
#include <math.h>

#define D_MODEL 512
#define NHEAD   8
#define HD      64
#define WIN     32
#define BATCH   2
#define SEQ     2048

// Scratch (no cudaMalloc allowed)
__device__ float g_q[BATCH * NHEAD * SEQ * HD];
__device__ float g_k[BATCH * NHEAD * SEQ * HD];
__device__ float g_v[BATCH * NHEAD * SEQ * HD];
__device__ float g_attn[BATCH * SEQ * D_MODEL];

__device__ __forceinline__ float f2tf32(float f) {
    unsigned int u;
    asm("cvt.rna.tf32.f32 %0, %1;" : "=r"(u) : "f"(f));
    return __uint_as_float(u);
}

__device__ __forceinline__ void mma_tf32(float4& d,
    unsigned int a0, unsigned int a1, unsigned int a2, unsigned int a3,
    unsigned int b0, unsigned int b1)
{
    asm volatile(
        "mma.sync.aligned.m16n8k8.row.col.f32.tf32.tf32.f32 "
        "{%0,%1,%2,%3}, {%4,%5,%6,%7}, {%8,%9}, {%0,%1,%2,%3};\n"
        : "+f"(d.x), "+f"(d.y), "+f"(d.z), "+f"(d.w)
        : "r"(a0), "r"(a1), "r"(a2), "r"(a3), "r"(b0), "r"(b1));
}

// ---------------------------------------------------------------------------
// TF32 tensor-core GEMM, double-buffered, A in fragment-major smem layout.
// BM=128, BK=32, 256 threads = 8 warps.
// A smem: per (16m x 8k) tile, 32 lanes x 4 slots contiguous (a0,a1,a2,a3),
//   tile stride 132 -> one LDS.128 per A-fragment, conflict-free.
// B smem: [k][n] stride BN_+8 -> 2 scalar LDS per B-fragment, conflict-free.
// ---------------------------------------------------------------------------
#define BM 128
#define BK 32
#define TILE_A 132
#define A_TK (BK / 8)                          // 4 k-tiles
#define AS_FLOATS ((BM / 16) * A_TK * TILE_A)  // 4224

template<int BN_, bool SCATTER>
__global__ __launch_bounds__(256, 2) void mma_gemm(
    const float* __restrict__ A, const float* __restrict__ Bw,
    const float* __restrict__ bias, float* __restrict__ C,
    float* __restrict__ qo, float* __restrict__ ko, float* __restrict__ vo,
    int M, int N, int K)
{
    constexpr int WM_WARPS = (BN_ == 128) ? 2 : 4;
    constexpr int WN_WARPS = 8 / WM_WARPS;
    constexpr int WT_M = BM / WM_WARPS;          // 64 or 32
    constexpr int WT_N = BN_ / WN_WARPS;         // 32
    constexpr int MF = WT_M / 16;                // 4 or 2
    constexpr int NF = WT_N / 8;                 // 4
    constexpr int BS_Sl = BN_ + 8;
    constexpr int BUF = AS_FLOATS + BK * BS_Sl;
    constexpr int BF4 = (BK * BN_) / 1024;
    constexpr int BROW_F4 = BN_ / 4;

    extern __shared__ float smbuf[];

    const int tid  = threadIdx.x;
    const int bm   = blockIdx.y * BM;
    const int bn   = blockIdx.x * BN_;
    const int w    = tid >> 5;
    const int wm   = w % WM_WARPS;
    const int wn   = w / WM_WARPS;
    const int lane = tid & 31;
    const int gid  = lane >> 2;
    const int tig  = lane & 3;

    float4 acc[MF][NF];
    #pragma unroll
    for (int i = 0; i < MF; i++)
        #pragma unroll
        for (int j = 0; j < NF; j++)
            acc[i][j] = make_float4(0.f, 0.f, 0.f, 0.f);

    float4 a_st[4], b_st[BF4];

    auto ldg_tiles = [&](int k0) {
        #pragma unroll
        for (int p = 0; p < 4; p++) {
            const int idx = p * 256 + tid;
            const int r = idx >> 3, c = (idx & 7) << 2;
            a_st[p] = *(const float4*)&A[(size_t)(bm + r) * K + k0 + c];
        }
        #pragma unroll
        for (int p = 0; p < BF4; p++) {
            const int idx = p * 256 + tid;
            const int r = idx / BROW_F4, c = (idx % BROW_F4) << 2;
            b_st[p] = *(const float4*)&Bw[(size_t)(k0 + r) * N + bn + c];
        }
    };
    auto sts_tiles = [&](float* base) {
        float* As = base;
        float* Bs = base + AS_FLOATS;
        // A: scatter into fragment-major tiles
        #pragma unroll
        for (int p = 0; p < 4; p++) {
            const int idx = p * 256 + tid;
            const int r = idx >> 3, c0 = (idx & 7) << 2;
            float4 t = a_st[p];
            const int m16 = r >> 4, k8 = c0 >> 3;
            const int slot = ((r >> 3) & 1) + ((c0 & 4) >> 1);
            float* dst = As + (m16 * A_TK + k8) * TILE_A + (r & 7) * 16 + slot;
            dst[0]  = f2tf32(t.x);
            dst[4]  = f2tf32(t.y);
            dst[8]  = f2tf32(t.z);
            dst[12] = f2tf32(t.w);
        }
        #pragma unroll
        for (int p = 0; p < BF4; p++) {
            const int idx = p * 256 + tid;
            const int r = idx / BROW_F4, c = (idx % BROW_F4) << 2;
            float4 t = b_st[p];
            t.x = f2tf32(t.x); t.y = f2tf32(t.y);
            t.z = f2tf32(t.z); t.w = f2tf32(t.w);
            *(float4*)&Bs[r * BS_Sl + c] = t;
        }
    };
    auto compute = [&](const float* base) {
        const float* As = base;
        const float* Bs = base + AS_FLOATS;
        #pragma unroll
        for (int ks = 0; ks < 4; ks++) {
            const int kk = ks * 8;
            unsigned int af[MF][4], bf[NF][2];
            #pragma unroll
            for (int mf = 0; mf < MF; mf++) {
                const float4 fa = *(const float4*)&As[
                    ((wm * MF + mf) * A_TK + ks) * TILE_A + lane * 4];
                af[mf][0] = __float_as_uint(fa.x);
                af[mf][1] = __float_as_uint(fa.y);
                af[mf][2] = __float_as_uint(fa.z);
                af[mf][3] = __float_as_uint(fa.w);
            }
            #pragma unroll
            for (int nf = 0; nf < NF; nf++) {
                const int nb = wn * WT_N + nf * 8;
                bf[nf][0] = __float_as_uint(Bs[(kk + tig)     * BS_Sl + nb + gid]);
                bf[nf][1] = __float_as_uint(Bs[(kk + tig + 4) * BS_Sl + nb + gid]);
            }
            #pragma unroll
            for (int mf = 0; mf < MF; mf++)
                #pragma unroll
                for (int nf = 0; nf < NF; nf++)
                    mma_tf32(acc[mf][nf],
                             af[mf][0], af[mf][1], af[mf][2], af[mf][3],
                             bf[nf][0], bf[nf][1]);
        }
    };

    const int NIT = K / BK;
    ldg_tiles(0);
    sts_tiles(smbuf);
    __syncthreads();
    int cur = 0;
    for (int it = 0; it < NIT; it++) {
        if (it + 1 < NIT) ldg_tiles((it + 1) * BK);
        compute(smbuf + cur * BUF);
        if (it + 1 < NIT) {
            sts_tiles(smbuf + (cur ^ 1) * BUF);
            __syncthreads();
            cur ^= 1;
        }
    }

    #pragma unroll
    for (int mf = 0; mf < MF; mf++) {
        #pragma unroll
        for (int nf = 0; nf < NF; nf++) {
            const int m0 = bm + wm * WT_M + mf * 16 + gid;
            const int n0 = bn + wn * WT_N + nf * 8 + tig * 2;
            const float bs0 = bias[n0], bs1 = bias[n0 + 1];
            float2 top = make_float2(acc[mf][nf].x + bs0, acc[mf][nf].y + bs1);
            float2 bot = make_float2(acc[mf][nf].z + bs0, acc[mf][nf].w + bs1);
            if (SCATTER) {
                const int t  = n0 >> 9;
                const int hh = (n0 >> 6) & 7;
                const int dd = n0 & 63;
                float* p = (t == 0) ? qo : (t == 1) ? ko : vo;
                {
                    const int bb = m0 >> 11, ss = m0 & 2047;
                    *(float2*)&p[((size_t)(bb * NHEAD + hh) * SEQ + ss) * HD + dd] = top;
                }
                {
                    const int m1 = m0 + 8;
                    const int bb = m1 >> 11, ss = m1 & 2047;
                    *(float2*)&p[((size_t)(bb * NHEAD + hh) * SEQ + ss) * HD + dd] = bot;
                }
            } else {
                *(float2*)&C[(size_t)m0 * N + n0]       = top;
                *(float2*)&C[(size_t)(m0 + 8) * N + n0] = bot;
            }
        }
    }
}

#define QKV_SMEM ((AS_FLOATS + BK * (128 + 8)) * 2 * 4)   // 68608
#define OUT_SMEM ((AS_FLOATS + BK * (64 + 8)) * 2 * 4)    // 52224

// ---------------------------------------------------------------------------
// Sliding-window attention, tf32 MMA (unchanged from R6).
// ---------------------------------------------------------------------------
#define TQ 64
#define TC 128
#define QS_S 68
#define KS_S 68
#define VS_S 72
#define P_S  132
#define KV_UNION (TC * VS_S)
#define ATTN_SMEM_FLOATS (TQ * QS_S + KV_UNION + TQ * P_S)
#define ATTN_SMEM_BYTES  (ATTN_SMEM_FLOATS * 4)

__global__ __launch_bounds__(256, 2) void window_attn_mma(
    const float* __restrict__ gq, const float* __restrict__ gk,
    const float* __restrict__ gv, float* __restrict__ out)
{
    const int s0  = blockIdx.x * TQ;
    const int h   = blockIdx.y;
    const int b   = blockIdx.z;
    const int tid = threadIdx.x;
    const size_t base = (size_t)(b * NHEAD + h) * SEQ;

    extern __shared__ float smem[];
    float* Qs = smem;
    float* KV = smem + TQ * QS_S;
    float* P  = KV + KV_UNION;

    const int d  = tid & 63;
    const int r0 = tid >> 6;
    const int w    = tid >> 5;
    const int lane = tid & 31;
    const int gid  = lane >> 2;
    const int tig  = lane & 3;
    const int wm   = w & 1;
    const int wn   = w >> 1;

    #pragma unroll
    for (int r = r0; r < TQ; r += 4)
        Qs[r * QS_S + d] = f2tf32(gq[(base + s0 + r) * HD + d] * 0.125f);
    #pragma unroll
    for (int c = r0; c < TC; c += 4) {
        const int idx = s0 - WIN + c;
        float val = 0.f;
        if (idx >= 0 && idx < SEQ) val = gk[(base + idx) * HD + d];
        KV[c * KS_S + d] = f2tf32(val);
    }
    __syncthreads();

    // GEMM1: S = Q @ K^T
    {
        float4 acc[2][4];
        #pragma unroll
        for (int i = 0; i < 2; i++)
            #pragma unroll
            for (int j = 0; j < 4; j++)
                acc[i][j] = make_float4(0.f, 0.f, 0.f, 0.f);

        #pragma unroll
        for (int ks = 0; ks < 8; ks++) {
            const int kk = ks * 8;
            unsigned int af[2][4], bf[4][2];
            #pragma unroll
            for (int mf = 0; mf < 2; mf++) {
                const int mb = wm * 32 + mf * 16;
                af[mf][0] = __float_as_uint(Qs[(mb + gid)     * QS_S + kk + tig]);
                af[mf][1] = __float_as_uint(Qs[(mb + gid + 8) * QS_S + kk + tig]);
                af[mf][2] = __float_as_uint(Qs[(mb + gid)     * QS_S + kk + tig + 4]);
                af[mf][3] = __float_as_uint(Qs[(mb + gid + 8) * QS_S + kk + tig + 4]);
            }
            #pragma unroll
            for (int nf = 0; nf < 4; nf++) {
                const int nb = wn * 32 + nf * 8;
                bf[nf][0] = __float_as_uint(KV[(nb + gid) * KS_S + kk + tig]);
                bf[nf][1] = __float_as_uint(KV[(nb + gid) * KS_S + kk + tig + 4]);
            }
            #pragma unroll
            for (int mf = 0; mf < 2; mf++)
                #pragma unroll
                for (int nf = 0; nf < 4; nf++)
                    mma_tf32(acc[mf][nf],
                             af[mf][0], af[mf][1], af[mf][2], af[mf][3],
                             bf[nf][0], bf[nf][1]);
        }
        #pragma unroll
        for (int mf = 0; mf < 2; mf++) {
            #pragma unroll
            for (int nf = 0; nf < 4; nf++) {
                const int m0 = wm * 32 + mf * 16 + gid;
                const int n0 = wn * 32 + nf * 8 + tig * 2;
                *(float2*)&P[m0 * P_S + n0]       = make_float2(acc[mf][nf].x, acc[mf][nf].y);
                *(float2*)&P[(m0 + 8) * P_S + n0] = make_float2(acc[mf][nf].z, acc[mf][nf].w);
            }
        }
    }
    __syncthreads();

    #pragma unroll
    for (int c = r0; c < TC; c += 4) {
        const int idx = s0 - WIN + c;
        float val = 0.f;
        if (idx >= 0 && idx < SEQ) val = gv[(base + idx) * HD + d];
        KV[c * VS_S + d] = f2tf32(val);
    }

    // Masked softmax
    {
        for (int q = w; q < TQ; q += 8) {
            float vals[4];
            #pragma unroll
            for (int k = 0; k < 4; k++) {
                const int c = lane + k * 32;
                const int idx = s0 - WIN + c;
                const bool valid = (c >= q) && (c <= q + 2 * WIN) && (idx >= 0) && (idx < SEQ);
                vals[k] = valid ? P[q * P_S + c] : -1e30f;
            }
            float m = fmaxf(fmaxf(vals[0], vals[1]), fmaxf(vals[2], vals[3]));
            #pragma unroll
            for (int off = 16; off > 0; off >>= 1)
                m = fmaxf(m, __shfl_xor_sync(0xffffffffu, m, off));
            float e[4], sum = 0.f;
            #pragma unroll
            for (int k = 0; k < 4; k++) { e[k] = __expf(vals[k] - m); sum += e[k]; }
            #pragma unroll
            for (int off = 16; off > 0; off >>= 1)
                sum += __shfl_xor_sync(0xffffffffu, sum, off);
            const float inv = 1.0f / sum;
            #pragma unroll
            for (int k = 0; k < 4; k++)
                P[q * P_S + lane + k * 32] = f2tf32(e[k] * inv);
        }
    }
    __syncthreads();

    // GEMM2: O = P @ V
    {
        float4 acc[2][2];
        #pragma unroll
        for (int i = 0; i < 2; i++)
            #pragma unroll
            for (int j = 0; j < 2; j++)
                acc[i][j] = make_float4(0.f, 0.f, 0.f, 0.f);

        #pragma unroll 4
        for (int ks = 0; ks < 16; ks++) {
            const int kk = ks * 8;
            unsigned int af[2][4], bf[2][2];
            #pragma unroll
            for (int mf = 0; mf < 2; mf++) {
                const int mb = wm * 32 + mf * 16;
                af[mf][0] = __float_as_uint(P[(mb + gid)     * P_S + kk + tig]);
                af[mf][1] = __float_as_uint(P[(mb + gid + 8) * P_S + kk + tig]);
                af[mf][2] = __float_as_uint(P[(mb + gid)     * P_S + kk + tig + 4]);
                af[mf][3] = __float_as_uint(P[(mb + gid + 8) * P_S + kk + tig + 4]);
            }
            #pragma unroll
            for (int nf = 0; nf < 2; nf++) {
                const int nb = wn * 16 + nf * 8;
                bf[nf][0] = __float_as_uint(KV[(kk + tig)     * VS_S + nb + gid]);
                bf[nf][1] = __float_as_uint(KV[(kk + tig + 4) * VS_S + nb + gid]);
            }
            #pragma unroll
            for (int mf = 0; mf < 2; mf++)
                #pragma unroll
                for (int nf = 0; nf < 2; nf++)
                    mma_tf32(acc[mf][nf],
                             af[mf][0], af[mf][1], af[mf][2], af[mf][3],
                             bf[nf][0], bf[nf][1]);
        }
        #pragma unroll
        for (int mf = 0; mf < 2; mf++) {
            #pragma unroll
            for (int nf = 0; nf < 2; nf++) {
                const int m0 = wm * 32 + mf * 16 + gid;
                const int n0 = wn * 16 + nf * 8 + tig * 2;
                size_t o0 = ((size_t)b * SEQ + s0 + m0) * D_MODEL + h * HD + n0;
                *(float2*)&out[o0] = make_float2(acc[mf][nf].x, acc[mf][nf].y);
                size_t o1 = ((size_t)b * SEQ + s0 + m0 + 8) * D_MODEL + h * HD + n0;
                *(float2*)&out[o1] = make_float2(acc[mf][nf].z, acc[mf][nf].w);
            }
        }
    }
}

// ---------------------------------------------------------------------------
extern "C" void kernel_launch(void* const* d_in, const int* in_sizes, int n_in,
                              void* d_out, int out_size)
{
    const float* x     = (const float*)d_in[0];
    const float* w_qkv = (const float*)d_in[1];
    const float* b_qkv = (const float*)d_in[2];
    const float* w_out = (const float*)d_in[3];
    const float* b_out = (const float*)d_in[4];
    float* out = (float*)d_out;

    float *q, *k, *v, *attn;
    cudaGetSymbolAddress((void**)&q,    g_q);
    cudaGetSymbolAddress((void**)&k,    g_k);
    cudaGetSymbolAddress((void**)&v,    g_v);
    cudaGetSymbolAddress((void**)&attn, g_attn);

    const int M = BATCH * SEQ;     // 4096
    const int K = D_MODEL;         // 512

    cudaFuncSetAttribute((const void*)mma_gemm<128, true>,
                         cudaFuncAttributeMaxDynamicSharedMemorySize, QKV_SMEM);
    cudaFuncSetAttribute((const void*)mma_gemm<64, false>,
                         cudaFuncAttributeMaxDynamicSharedMemorySize, OUT_SMEM);
    cudaFuncSetAttribute(window_attn_mma,
                         cudaFuncAttributeMaxDynamicSharedMemorySize, ATTN_SMEM_BYTES);

    // 1) QKV projection (tf32 MMA, frag-major A) with head-major scatter
    {
        dim3 grid((3 * D_MODEL) / 128, M / BM);   // 12 x 32 = 384 CTAs
        mma_gemm<128, true><<<grid, 256, QKV_SMEM>>>(
            x, w_qkv, b_qkv, nullptr, q, k, v, M, 3 * D_MODEL, K);
    }
    // 2) Windowed attention (tf32 MMA)
    {
        dim3 grid(SEQ / TQ, NHEAD, BATCH);        // 512 CTAs
        window_attn_mma<<<grid, 256, ATTN_SMEM_BYTES>>>(q, k, v, attn);
    }
    // 3) Output projection (tf32 MMA)
    {
        dim3 grid(D_MODEL / 64, M / BM);          // 256 CTAs
        mma_gemm<64, false><<<grid, 256, OUT_SMEM>>>(
            attn, w_out, b_out, out, nullptr, nullptr, nullptr,
            M, D_MODEL, K);
    }
}